// round 1
// baseline (speedup 1.0000x reference)
#include <cuda_runtime.h>

// fusedmax(x) = sparsemax(prox_TV1D(x, alpha=1)), row-wise.
// B=4096 rows, N=512 cols, fp32.
//
// Layout: 128 blocks x 32 threads. Each thread owns one row, staged
// transposed in shared memory with pad-33 (conflict-free for divergent
// per-lane column walks AND for the coalesced load/store loops).

#define NROWS 4096
#define NCOLS 512
#define ROWS_PER_BLK 32
#define PAD 33
#define SMEM_BYTES (NCOLS * PAD * 4)

__global__ __launch_bounds__(32, 1)
void fusedmax_kernel(const float* __restrict__ x, float* __restrict__ out) {
    extern __shared__ float ys[];            // [NCOLS][PAD], ys[c*PAD + lane]
    __shared__ float taus[ROWS_PER_BLK];

    const int lane    = threadIdx.x;
    const int rowBase = blockIdx.x * ROWS_PER_BLK;
    const float lam   = 1.0f;
    const int n       = NCOLS;

    // ---- coalesced load, transposed into shared ----
    const float* src = x + (size_t)rowBase * NCOLS;
    #pragma unroll 4
    for (int j = 0; j < ROWS_PER_BLK * NCOLS; j += 32) {
        int idx = j + lane;
        int r = idx >> 9;          // idx / 512
        int c = idx & (NCOLS - 1); // idx % 512
        ys[c * PAD + r] = src[idx];
    }
    __syncwarp();

    // ---- Condat TV1D (faithful port of the JAX body), in-place ----
    // In-place safety: every flush writes [k0, hi] and the next read index
    // nk is hi+1, except when clamped to n-1 — so cache y[n-1] in a register.
    const float ylast = ys[(n - 1) * PAD + lane];
    const float y0    = ys[0 * PAD + lane];

    int   k = 0, k0 = 0, km = 0, kp = 0;
    float vmin = y0 - lam, vmax = y0 + lam;
    float umin = lam, umax = -lam;
    bool  done = false;

    while (!done) {
        const bool at_end = (k == n - 1);
        const int  kn1    = (k + 1 < n - 1) ? (k + 1) : (n - 1);
        const float ynext = (kn1 == n - 1) ? ylast : ys[kn1 * PAD + lane];

        const bool neg = at_end ? (umin < 0.0f) : (ynext + umin < vmin - lam);
        const bool pos = !neg && (at_end ? (umax > 0.0f)
                                         : (ynext + umax > vmax + lam));
        const bool mid = !neg && !pos;
        const bool fin = mid && at_end;

        // flush a finished segment
        if (neg | pos | fin) {
            const int hi = neg ? km : (pos ? kp : n - 1);
            const float val = pos ? vmax
                                  : (fin ? vmin + umin / (float)(k - k0 + 1)
                                         : vmin);
            for (int i = k0; i <= hi; i++) ys[i * PAD + lane] = val;
        }

        int nk = neg ? (km + 1) : (pos ? (kp + 1) : (k + 1));
        nk = (nk < n - 1) ? nk : (n - 1);
        const float ynk = (nk == n - 1) ? ylast : ys[nk * PAD + lane];

        // plain accumulation step (all from OLD state)
        const float umin_t = umin + ynk - vmin;
        const float umax_t = umax + ynk - vmax;
        const float cnt    = (float)(nk - k0 + 1);
        const bool  c1 = (umin_t >= lam);
        const bool  c2 = (umax_t <= -lam);
        const float vmin_mid = c1 ? vmin + (umin_t - lam) / cnt : vmin;
        const float umin_mid = c1 ? lam : umin_t;
        const int   km_mid   = c1 ? nk : km;
        const float vmax_mid = c2 ? vmax + (umax_t + lam) / cnt : vmax;
        const float umax_mid = c2 ? -lam : umax_t;
        const int   kp_mid   = c2 ? nk : kp;

        const bool mneg = neg && !at_end;
        const bool mpos = pos && !at_end;
        const bool mmid = mid && !at_end;
        const bool eneg = neg && at_end;
        const bool epos = pos && at_end;
        const bool jump = neg | pos;

        const int   nk0 = jump ? nk : k0;
        const int   nkm = (neg | mpos) ? nk : (mmid ? km_mid : km);
        const int   nkp = (pos | mneg) ? nk : (mmid ? kp_mid : kp);
        const float nvmin = neg ? ynk
                          : (mpos ? ynk - 2.0f * lam
                          : (mmid ? vmin_mid : vmin));
        const float nvmax = pos ? ynk
                          : (mneg ? ynk + 2.0f * lam
                          : (mmid ? vmax_mid : vmax));
        const float numin = (neg | mpos) ? lam
                          : (epos ? ynk - lam - vmin
                          : (mmid ? umin_mid : umin));
        const float numax = (pos | mneg) ? -lam
                          : (eneg ? ynk + lam - vmax
                          : (mmid ? umax_mid : umax));

        k    = fin ? k : nk;
        k0   = nk0;  km = nkm;  kp = nkp;
        vmin = nvmin; vmax = nvmax; umin = numin; umax = numax;
        done = fin;
    }
    __syncwarp();

    // ---- sparsemax threshold via Michelot (exact fixed point) ----
    {
        float sum = 0.0f;
        for (int i = 0; i < n; i++) sum += ys[i * PAD + lane];
        float tau = (sum - 1.0f) / (float)n;
        int c_prev = n;
        for (int it = 0; it < n; it++) {
            float s = 0.0f;
            int   c = 0;
            for (int i = 0; i < n; i++) {
                float v = ys[i * PAD + lane];
                if (v > tau) { s += v; c++; }
            }
            if (c == c_prev) break;      // support stable -> tau is final
            tau = (s - 1.0f) / (float)c;
            c_prev = c;
        }
        taus[lane] = tau;
    }
    __syncwarp();

    // ---- coalesced store of max(z - tau, 0) ----
    float* dst = out + (size_t)rowBase * NCOLS;
    #pragma unroll 4
    for (int j = 0; j < ROWS_PER_BLK * NCOLS; j += 32) {
        int idx = j + lane;
        int r = idx >> 9;
        int c = idx & (NCOLS - 1);
        float v = ys[c * PAD + r] - taus[r];
        dst[idx] = (v > 0.0f) ? v : 0.0f;
    }
}

extern "C" void kernel_launch(void* const* d_in, const int* in_sizes, int n_in,
                              void* d_out, int out_size) {
    (void)in_sizes; (void)n_in; (void)out_size;
    const float* x   = (const float*)d_in[0];
    float*       out = (float*)d_out;

    cudaFuncSetAttribute(fusedmax_kernel,
                         cudaFuncAttributeMaxDynamicSharedMemorySize,
                         SMEM_BYTES);
    fusedmax_kernel<<<NROWS / ROWS_PER_BLK, ROWS_PER_BLK, SMEM_BYTES>>>(x, out);
}